// round 13
// baseline (speedup 1.0000x reference)
#include <cuda_runtime.h>
#include <cuda_bf16.h>
#include <cstdint>

// YOLO layer: (B, 3*85, 76, 76) fp32 -> (B, 3*76*76, 85) fp32
// HBM-bound transpose + elementwise epilogue. Final shape (round-5 winner):
//   TPB=512, one (b,anchor,row) per CTA, 4 front-batched vec4 __ldcs
//   LDG.128s per thread (high MLP), transform + smem scatter into output
//   order (stride 85, conflict-free), single thread-0 cp.async.bulk store.
// Only delta vs round 5: wait_group.read (release CTA when SMEM is read by
// the copy engine, not when the HBM write completes) + launch_bounds(512,4)
// pinning the 32-reg / 4-CTA-per-SM operating point.

#define G     76
#define C     85
#define NA    3
#define TPB   512
#define TILE  (C * G)         // 6460 floats (25840 B)
#define TILE4 (TILE / 4)      // 1615 vec4
#define VPC   (G / 4)         // 19 vec4 per channel row
#define NIT   4               // 512*4 = 2048 >= 1615

__device__ __forceinline__ float sigf(float v) {
    return __fdividef(1.0f, 1.0f + __expf(-v));
}

__global__ __launch_bounds__(TPB, 4)
void yolo_kernel(const float* __restrict__ in,
                 const void*  __restrict__ imgdim_p,
                 float* __restrict__ out)
{
    __shared__ __align__(16) float tile[TILE];

    const int blk = blockIdx.x;
    const int t   = blk % G;              // grid row (grid_y)
    const int a   = (blk / G) % NA;       // anchor
    const int b   = blk / (G * NA);       // batch

    float stride = 8.0f;
    if (imgdim_p) {
        int iv = *(const int*)imgdim_p;
        float dim = (iv > 0 && iv < (1 << 20)) ? (float)iv : __int_as_float(iv);
        stride = dim / (float)G;
    }

    const float AW[NA] = {116.0f, 156.0f, 373.0f};
    const float AH[NA] = { 90.0f, 198.0f, 326.0f};
    const float aw = AW[a], ah = AH[a];
    const float gy = (float)t;

    const float* base = in + ((size_t)(b * NA + a) * C) * (G * G) + (size_t)t * G;

    // ---- phase 1: batch all loads (4 independent LDG.128 in flight) ----
    float4 v[NIT];
    #pragma unroll
    for (int j = 0; j < NIT; j++) {
        const unsigned i = threadIdx.x + j * TPB;
        if (i < TILE4) {
            const unsigned k = i / VPC;
            const unsigned q = i - k * VPC;
            v[j] = __ldcs((const float4*)(base + (size_t)k * (G * G)) + q);
        }
    }

    // ---- phase 2: transform + scatter to smem in output order ----
    #pragma unroll
    for (int j = 0; j < NIT; j++) {
        const unsigned i = threadIdx.x + j * TPB;
        if (i < TILE4) {
            const unsigned k = i / VPC;        // channel 0..84
            const unsigned q = i - k * VPC;    // vec4 index 0..18
            const int s0 = q * 4;
            const float4 w = v[j];

            float r0, r1, r2, r3;
            if (k >= 4) {
                r0 = sigf(w.x); r1 = sigf(w.y); r2 = sigf(w.z); r3 = sigf(w.w);
            } else if (k == 0) {
                r0 = (sigf(w.x) + (float)(s0 + 0)) * stride;
                r1 = (sigf(w.y) + (float)(s0 + 1)) * stride;
                r2 = (sigf(w.z) + (float)(s0 + 2)) * stride;
                r3 = (sigf(w.w) + (float)(s0 + 3)) * stride;
            } else if (k == 1) {
                r0 = (sigf(w.x) + gy) * stride;
                r1 = (sigf(w.y) + gy) * stride;
                r2 = (sigf(w.z) + gy) * stride;
                r3 = (sigf(w.w) + gy) * stride;
            } else if (k == 2) {
                r0 = __expf(w.x) * aw; r1 = __expf(w.y) * aw;
                r2 = __expf(w.z) * aw; r3 = __expf(w.w) * aw;
            } else {
                r0 = __expf(w.x) * ah; r1 = __expf(w.y) * ah;
                r2 = __expf(w.z) * ah; r3 = __expf(w.w) * ah;
            }
            float* p = &tile[(unsigned)s0 * C + k];
            p[0]     = r0;
            p[C]     = r1;
            p[2 * C] = r2;
            p[3 * C] = r3;
        }
    }
    __syncthreads();

    // ---- phase 3: single bulk async store; release when SMEM is read ----
    if (threadIdx.x == 0) {
        float* obase = out + ((size_t)(b * NA + a) * (G * G) + (size_t)t * G) * C;
        uint32_t saddr;
        asm("{ .reg .u64 t0; cvta.to.shared.u64 t0, %1; cvt.u32.u64 %0, t0; }"
            : "=r"(saddr) : "l"(tile));
        asm volatile("fence.proxy.async.shared::cta;" ::: "memory");
        asm volatile("cp.async.bulk.global.shared::cta.bulk_group [%0], [%1], %2;"
                     :: "l"(obase), "r"(saddr), "n"(TILE * 4) : "memory");
        asm volatile("cp.async.bulk.commit_group;" ::: "memory");
        asm volatile("cp.async.bulk.wait_group.read 0;" ::: "memory");
    }
}

extern "C" void kernel_launch(void* const* d_in, const int* in_sizes, int n_in,
                              void* d_out, int out_size)
{
    const float* x = (const float*)d_in[0];
    const void*  dim = (n_in > 1) ? d_in[1] : nullptr;
    const int B = in_sizes[0] / (NA * C * G * G);   // 64 for the bench shape

    dim3 grid(B * NA * G);
    yolo_kernel<<<grid, TPB>>>(x, dim, (float*)d_out);
}

// round 14
// speedup vs baseline: 1.0655x; 1.0655x over previous
#include <cuda_runtime.h>
#include <cuda_bf16.h>
#include <cstdint>

// YOLO layer: (B, 3*85, 76, 76) fp32 -> (B, 3*76*76, 85) fp32
// HBM-bound transpose + elementwise epilogue. CONVERGED OPTIMUM (round 5):
//   - one (b, anchor, grid-row) slice per CTA: 85 channels x 76 cols
//   - phase 1: each thread front-batches 4 independent vec4 __ldcs LDG.128s
//     (MLP is the binding lever on this kernel; evict-first keeps L2 for the
//     write stream)
//   - phase 2: transform + smem scatter into output order (stride 85 = odd
//     -> conflict-free)
//   - phase 3: SINGLE thread-0 cp.async.bulk smem->gmem store with FULL
//     wait_group 0: the drain-wait phase-separates this SM's read bursts
//     from its write drains (early-release/.read variants measurably lose
//     to HBM read/write turnaround mixing)
//   - 32 regs, 26KB smem, TPB=512 -> 4 CTAs/SM = 2048 thr/SM
// Measured: 116.9us, DRAM 77.8%, ~6.45 TB/s effective on 754MB round-trip.

#define G     76
#define C     85
#define NA    3
#define TPB   512
#define TILE  (C * G)         // 6460 floats (25840 B)
#define TILE4 (TILE / 4)      // 1615 vec4
#define VPC   (G / 4)         // 19 vec4 per channel row
#define NIT   4               // 512*4 = 2048 >= 1615

__device__ __forceinline__ float sigf(float v) {
    return __fdividef(1.0f, 1.0f + __expf(-v));
}

__global__ __launch_bounds__(TPB)
void yolo_kernel(const float* __restrict__ in,
                 const void*  __restrict__ imgdim_p,
                 float* __restrict__ out)
{
    __shared__ __align__(16) float tile[TILE];

    const int blk = blockIdx.x;
    const int t   = blk % G;              // grid row (grid_y)
    const int a   = (blk / G) % NA;       // anchor
    const int b   = blk / (G * NA);       // batch

    float stride = 8.0f;
    if (imgdim_p) {
        int iv = *(const int*)imgdim_p;
        float dim = (iv > 0 && iv < (1 << 20)) ? (float)iv : __int_as_float(iv);
        stride = dim / (float)G;
    }

    const float AW[NA] = {116.0f, 156.0f, 373.0f};
    const float AH[NA] = { 90.0f, 198.0f, 326.0f};
    const float aw = AW[a], ah = AH[a];
    const float gy = (float)t;

    const float* base = in + ((size_t)(b * NA + a) * C) * (G * G) + (size_t)t * G;

    // ---- phase 1: batch all loads (4 independent LDG.128 in flight) ----
    float4 v[NIT];
    #pragma unroll
    for (int j = 0; j < NIT; j++) {
        const unsigned i = threadIdx.x + j * TPB;
        if (i < TILE4) {
            const unsigned k = i / VPC;
            const unsigned q = i - k * VPC;
            v[j] = __ldcs((const float4*)(base + (size_t)k * (G * G)) + q);
        }
    }

    // ---- phase 2: transform + scatter to smem in output order ----
    #pragma unroll
    for (int j = 0; j < NIT; j++) {
        const unsigned i = threadIdx.x + j * TPB;
        if (i < TILE4) {
            const unsigned k = i / VPC;        // channel 0..84
            const unsigned q = i - k * VPC;    // vec4 index 0..18
            const int s0 = q * 4;
            const float4 w = v[j];

            float r0, r1, r2, r3;
            if (k >= 4) {
                r0 = sigf(w.x); r1 = sigf(w.y); r2 = sigf(w.z); r3 = sigf(w.w);
            } else if (k == 0) {
                r0 = (sigf(w.x) + (float)(s0 + 0)) * stride;
                r1 = (sigf(w.y) + (float)(s0 + 1)) * stride;
                r2 = (sigf(w.z) + (float)(s0 + 2)) * stride;
                r3 = (sigf(w.w) + (float)(s0 + 3)) * stride;
            } else if (k == 1) {
                r0 = (sigf(w.x) + gy) * stride;
                r1 = (sigf(w.y) + gy) * stride;
                r2 = (sigf(w.z) + gy) * stride;
                r3 = (sigf(w.w) + gy) * stride;
            } else if (k == 2) {
                r0 = __expf(w.x) * aw; r1 = __expf(w.y) * aw;
                r2 = __expf(w.z) * aw; r3 = __expf(w.w) * aw;
            } else {
                r0 = __expf(w.x) * ah; r1 = __expf(w.y) * ah;
                r2 = __expf(w.z) * ah; r3 = __expf(w.w) * ah;
            }
            float* p = &tile[(unsigned)s0 * C + k];
            p[0]     = r0;
            p[C]     = r1;
            p[2 * C] = r2;
            p[3 * C] = r3;
        }
    }
    __syncthreads();

    // ---- phase 3: single bulk async store of the contiguous output block ----
    if (threadIdx.x == 0) {
        float* obase = out + ((size_t)(b * NA + a) * (G * G) + (size_t)t * G) * C;
        uint32_t saddr;
        asm("{ .reg .u64 t0; cvta.to.shared.u64 t0, %1; cvt.u32.u64 %0, t0; }"
            : "=r"(saddr) : "l"(tile));
        asm volatile("fence.proxy.async.shared::cta;" ::: "memory");
        asm volatile("cp.async.bulk.global.shared::cta.bulk_group [%0], [%1], %2;"
                     :: "l"(obase), "r"(saddr), "n"(TILE * 4) : "memory");
        asm volatile("cp.async.bulk.commit_group;" ::: "memory");
        asm volatile("cp.async.bulk.wait_group 0;" ::: "memory");
    }
}

extern "C" void kernel_launch(void* const* d_in, const int* in_sizes, int n_in,
                              void* d_out, int out_size)
{
    const float* x = (const float*)d_in[0];
    const void*  dim = (n_in > 1) ? d_in[1] : nullptr;
    const int B = in_sizes[0] / (NA * C * G * G);   // 64 for the bench shape

    dim3 grid(B * NA * G);
    yolo_kernel<<<grid, TPB>>>(x, dim, (float*)d_out);
}

// round 15
// speedup vs baseline: 1.1097x; 1.0415x over previous
#include <cuda_runtime.h>
#include <cuda_bf16.h>
#include <cstdint>

// YOLO layer: (B, 3*85, 76, 76) fp32 -> (B, 3*76*76, 85) fp32
// HBM-bound transpose + elementwise epilogue. Converged round-5 shape:
//   - one (b, anchor, grid-row) slice per CTA: 85 channels x 76 cols
//   - phase 1: 4 front-batched vec4 __ldcs LDG.128s per thread (MLP lever)
//   - phase 2: transform + smem scatter into output order (stride 85, odd
//     -> conflict-free)
//   - phase 3: single thread-0 cp.async.bulk store, full wait_group 0
//     (drain-wait phase-separates read bursts from write drains)
// Delta this round (epilogue-only): L2::cache_hint evict_first on the bulk
// store — written lines are dead after HBM drain; don't let them displace
// the read stream's boundary sectors in L2.
//   32 regs, 26KB smem, TPB=512 -> 4 CTAs/SM = 2048 thr/SM.

#define G     76
#define C     85
#define NA    3
#define TPB   512
#define TILE  (C * G)         // 6460 floats (25840 B)
#define TILE4 (TILE / 4)      // 1615 vec4
#define VPC   (G / 4)         // 19 vec4 per channel row
#define NIT   4               // 512*4 = 2048 >= 1615

__device__ __forceinline__ float sigf(float v) {
    return __fdividef(1.0f, 1.0f + __expf(-v));
}

__global__ __launch_bounds__(TPB)
void yolo_kernel(const float* __restrict__ in,
                 const void*  __restrict__ imgdim_p,
                 float* __restrict__ out)
{
    __shared__ __align__(16) float tile[TILE];

    const int blk = blockIdx.x;
    const int t   = blk % G;              // grid row (grid_y)
    const int a   = (blk / G) % NA;       // anchor
    const int b   = blk / (G * NA);       // batch

    float stride = 8.0f;
    if (imgdim_p) {
        int iv = *(const int*)imgdim_p;
        float dim = (iv > 0 && iv < (1 << 20)) ? (float)iv : __int_as_float(iv);
        stride = dim / (float)G;
    }

    const float AW[NA] = {116.0f, 156.0f, 373.0f};
    const float AH[NA] = { 90.0f, 198.0f, 326.0f};
    const float aw = AW[a], ah = AH[a];
    const float gy = (float)t;

    const float* base = in + ((size_t)(b * NA + a) * C) * (G * G) + (size_t)t * G;

    // ---- phase 1: batch all loads (4 independent LDG.128 in flight) ----
    float4 v[NIT];
    #pragma unroll
    for (int j = 0; j < NIT; j++) {
        const unsigned i = threadIdx.x + j * TPB;
        if (i < TILE4) {
            const unsigned k = i / VPC;
            const unsigned q = i - k * VPC;
            v[j] = __ldcs((const float4*)(base + (size_t)k * (G * G)) + q);
        }
    }

    // ---- phase 2: transform + scatter to smem in output order ----
    #pragma unroll
    for (int j = 0; j < NIT; j++) {
        const unsigned i = threadIdx.x + j * TPB;
        if (i < TILE4) {
            const unsigned k = i / VPC;        // channel 0..84
            const unsigned q = i - k * VPC;    // vec4 index 0..18
            const int s0 = q * 4;
            const float4 w = v[j];

            float r0, r1, r2, r3;
            if (k >= 4) {
                r0 = sigf(w.x); r1 = sigf(w.y); r2 = sigf(w.z); r3 = sigf(w.w);
            } else if (k == 0) {
                r0 = (sigf(w.x) + (float)(s0 + 0)) * stride;
                r1 = (sigf(w.y) + (float)(s0 + 1)) * stride;
                r2 = (sigf(w.z) + (float)(s0 + 2)) * stride;
                r3 = (sigf(w.w) + (float)(s0 + 3)) * stride;
            } else if (k == 1) {
                r0 = (sigf(w.x) + gy) * stride;
                r1 = (sigf(w.y) + gy) * stride;
                r2 = (sigf(w.z) + gy) * stride;
                r3 = (sigf(w.w) + gy) * stride;
            } else if (k == 2) {
                r0 = __expf(w.x) * aw; r1 = __expf(w.y) * aw;
                r2 = __expf(w.z) * aw; r3 = __expf(w.w) * aw;
            } else {
                r0 = __expf(w.x) * ah; r1 = __expf(w.y) * ah;
                r2 = __expf(w.z) * ah; r3 = __expf(w.w) * ah;
            }
            float* p = &tile[(unsigned)s0 * C + k];
            p[0]     = r0;
            p[C]     = r1;
            p[2 * C] = r2;
            p[3 * C] = r3;
        }
    }
    __syncthreads();

    // ---- phase 3: single bulk async store, write lines tagged evict-first ----
    if (threadIdx.x == 0) {
        float* obase = out + ((size_t)(b * NA + a) * (G * G) + (size_t)t * G) * C;
        uint32_t saddr;
        asm("{ .reg .u64 t0; cvta.to.shared.u64 t0, %1; cvt.u32.u64 %0, t0; }"
            : "=r"(saddr) : "l"(tile));
        asm volatile("fence.proxy.async.shared::cta;" ::: "memory");
        asm volatile(
            "{\n\t"
            ".reg .b64 pol;\n\t"
            "createpolicy.fractional.L2::evict_first.b64 pol, 1.0;\n\t"
            "cp.async.bulk.global.shared::cta.bulk_group.L2::cache_hint "
            "[%0], [%1], %2, pol;\n\t"
            "}"
            :: "l"(obase), "r"(saddr), "n"(TILE * 4) : "memory");
        asm volatile("cp.async.bulk.commit_group;" ::: "memory");
        asm volatile("cp.async.bulk.wait_group 0;" ::: "memory");
    }
}

extern "C" void kernel_launch(void* const* d_in, const int* in_sizes, int n_in,
                              void* d_out, int out_size)
{
    const float* x = (const float*)d_in[0];
    const void*  dim = (n_in > 1) ? d_in[1] : nullptr;
    const int B = in_sizes[0] / (NA * C * G * G);   // 64 for the bench shape

    dim3 grid(B * NA * G);
    yolo_kernel<<<grid, TPB>>>(x, dim, (float*)d_out);
}

// round 17
// speedup vs baseline: 1.1218x; 1.0109x over previous
#include <cuda_runtime.h>
#include <cuda_bf16.h>
#include <cstdint>

// YOLO layer: (B, 3*85, 76, 76) fp32 -> (B, 3*76*76, 85) fp32
// HBM-bound transpose + elementwise epilogue. Converged shape (R5 + R15):
//   - one (b, anchor, grid-row) slice per CTA: 85 channels x 76 cols
//   - phase 1: 4 front-batched vec4 streaming loads per thread (MLP lever),
//     .cs cache-op (the sm_103a-legal streaming spelling) + L2::256B
//     prefetch: sibling-row CTAs find their leading sectors already in L2
//   - phase 2: transform + smem scatter into output order (stride 85, odd
//     -> conflict-free)
//   - phase 3: single thread-0 cp.async.bulk store, write lines tagged
//     L2::evict_first (dead after HBM drain), full wait_group 0 (drain-wait
//     phase-separates read bursts from write drains — measured best)
//   32 regs, 26KB smem, TPB=512 -> 4 CTAs/SM = 2048 thr/SM.
// History: 116.9 (R5) -> 112.6 (R15 write hint). This round: read prefetch.

#define G     76
#define C     85
#define NA    3
#define TPB   512
#define TILE  (C * G)         // 6460 floats (25840 B)
#define TILE4 (TILE / 4)      // 1615 vec4
#define VPC   (G / 4)         // 19 vec4 per channel row
#define NIT   4               // 512*4 = 2048 >= 1615

__device__ __forceinline__ float sigf(float v) {
    return __fdividef(1.0f, 1.0f + __expf(-v));
}

// streaming (.cs) vec4 load with 256B L2 prefetch window
__device__ __forceinline__ float4 ldcs_pf256(const float4* p) {
    float4 r;
    asm("ld.global.cs.L2::256B.v4.f32 {%0,%1,%2,%3}, [%4];"
        : "=f"(r.x), "=f"(r.y), "=f"(r.z), "=f"(r.w) : "l"(p));
    return r;
}

__global__ __launch_bounds__(TPB)
void yolo_kernel(const float* __restrict__ in,
                 const void*  __restrict__ imgdim_p,
                 float* __restrict__ out)
{
    __shared__ __align__(16) float tile[TILE];

    const int blk = blockIdx.x;
    const int t   = blk % G;              // grid row (grid_y)
    const int a   = (blk / G) % NA;       // anchor
    const int b   = blk / (G * NA);       // batch

    float stride = 8.0f;
    if (imgdim_p) {
        int iv = *(const int*)imgdim_p;
        float dim = (iv > 0 && iv < (1 << 20)) ? (float)iv : __int_as_float(iv);
        stride = dim / (float)G;
    }

    const float AW[NA] = {116.0f, 156.0f, 373.0f};
    const float AH[NA] = { 90.0f, 198.0f, 326.0f};
    const float aw = AW[a], ah = AH[a];
    const float gy = (float)t;

    const float* base = in + ((size_t)(b * NA + a) * C) * (G * G) + (size_t)t * G;

    // ---- phase 1: batch all loads (4 independent LDG.128 in flight) ----
    float4 v[NIT];
    #pragma unroll
    for (int j = 0; j < NIT; j++) {
        const unsigned i = threadIdx.x + j * TPB;
        if (i < TILE4) {
            const unsigned k = i / VPC;
            const unsigned q = i - k * VPC;
            v[j] = ldcs_pf256((const float4*)(base + (size_t)k * (G * G)) + q);
        }
    }

    // ---- phase 2: transform + scatter to smem in output order ----
    #pragma unroll
    for (int j = 0; j < NIT; j++) {
        const unsigned i = threadIdx.x + j * TPB;
        if (i < TILE4) {
            const unsigned k = i / VPC;        // channel 0..84
            const unsigned q = i - k * VPC;    // vec4 index 0..18
            const int s0 = q * 4;
            const float4 w = v[j];

            float r0, r1, r2, r3;
            if (k >= 4) {
                r0 = sigf(w.x); r1 = sigf(w.y); r2 = sigf(w.z); r3 = sigf(w.w);
            } else if (k == 0) {
                r0 = (sigf(w.x) + (float)(s0 + 0)) * stride;
                r1 = (sigf(w.y) + (float)(s0 + 1)) * stride;
                r2 = (sigf(w.z) + (float)(s0 + 2)) * stride;
                r3 = (sigf(w.w) + (float)(s0 + 3)) * stride;
            } else if (k == 1) {
                r0 = (sigf(w.x) + gy) * stride;
                r1 = (sigf(w.y) + gy) * stride;
                r2 = (sigf(w.z) + gy) * stride;
                r3 = (sigf(w.w) + gy) * stride;
            } else if (k == 2) {
                r0 = __expf(w.x) * aw; r1 = __expf(w.y) * aw;
                r2 = __expf(w.z) * aw; r3 = __expf(w.w) * aw;
            } else {
                r0 = __expf(w.x) * ah; r1 = __expf(w.y) * ah;
                r2 = __expf(w.z) * ah; r3 = __expf(w.w) * ah;
            }
            float* p = &tile[(unsigned)s0 * C + k];
            p[0]     = r0;
            p[C]     = r1;
            p[2 * C] = r2;
            p[3 * C] = r3;
        }
    }
    __syncthreads();

    // ---- phase 3: single bulk async store, write lines tagged evict-first ----
    if (threadIdx.x == 0) {
        float* obase = out + ((size_t)(b * NA + a) * (G * G) + (size_t)t * G) * C;
        uint32_t saddr;
        asm("{ .reg .u64 t0; cvta.to.shared.u64 t0, %1; cvt.u32.u64 %0, t0; }"
            : "=r"(saddr) : "l"(tile));
        asm volatile("fence.proxy.async.shared::cta;" ::: "memory");
        asm volatile(
            "{\n\t"
            ".reg .b64 pol;\n\t"
            "createpolicy.fractional.L2::evict_first.b64 pol, 1.0;\n\t"
            "cp.async.bulk.global.shared::cta.bulk_group.L2::cache_hint "
            "[%0], [%1], %2, pol;\n\t"
            "}"
            :: "l"(obase), "r"(saddr), "n"(TILE * 4) : "memory");
        asm volatile("cp.async.bulk.commit_group;" ::: "memory");
        asm volatile("cp.async.bulk.wait_group 0;" ::: "memory");
    }
}

extern "C" void kernel_launch(void* const* d_in, const int* in_sizes, int n_in,
                              void* d_out, int out_size)
{
    const float* x = (const float*)d_in[0];
    const void*  dim = (n_in > 1) ? d_in[1] : nullptr;
    const int B = in_sizes[0] / (NA * C * G * G);   // 64 for the bench shape

    dim3 grid(B * NA * G);
    yolo_kernel<<<grid, TPB>>>(x, dim, (float*)d_out);
}